// round 5
// baseline (speedup 1.0000x reference)
#include <cuda_runtime.h>
#include <math.h>
#include <stdint.h>

#define B_  2
#define L_  2048
#define D_  2048
#define HD_ 64
#define NH_ 32
#define DC_ 2048
#define EPS 1.1920929e-7f

// ---------------- scratch (device globals; no allocation) ----------------
__device__ float g_ss [B_ * 2 * D_];                 // [b][4096] shift|scale
__device__ float g_h  [(size_t)B_ * L_ * D_];        // modulated hidden (tf32)
__device__ float g_qkv[(size_t)B_ * L_ * 3 * D_];    // fused qkv rows=(b,l)
__device__ float g_q  [(size_t)B_ * NH_ * L_ * HD_]; // [b][h][l][d]
__device__ float g_k  [(size_t)B_ * NH_ * L_ * HD_];
__device__ float g_v  [(size_t)B_ * NH_ * L_ * HD_];
__device__ float g_o  [(size_t)B_ * L_ * D_];        // attn out (tf32)
__device__ float g_wq [(size_t)3 * D_ * D_];         // w_qkv rounded to tf32
__device__ float g_wo [(size_t)D_ * D_];             // w_out rounded to tf32

// ---------------- tf32 helpers ------------------------------------------
__device__ __forceinline__ uint32_t f2tf32(float x) {
    uint32_t u;
    asm("cvt.rna.tf32.f32 %0, %1;" : "=r"(u) : "f"(x));
    return u;
}

__device__ __forceinline__ void mma_tf32(float* c, const uint32_t* a,
                                         const uint32_t* b) {
    asm volatile(
        "mma.sync.aligned.m16n8k8.row.col.f32.tf32.tf32.f32 "
        "{%0,%1,%2,%3}, {%4,%5,%6,%7}, {%8,%9}, {%0,%1,%2,%3};"
        : "+f"(c[0]), "+f"(c[1]), "+f"(c[2]), "+f"(c[3])
        : "r"(a[0]), "r"(a[1]), "r"(a[2]), "r"(a[3]), "r"(b[0]), "r"(b[1]));
}

// ---------------- one-shot weight rounding to tf32 -----------------------
__global__ void cvtw_kernel(float* __restrict__ dst, const float* __restrict__ src) {
    int i = (blockIdx.x * 256 + threadIdx.x) * 4;
    float4 v = *reinterpret_cast<const float4*>(src + i);
    uint4 u = make_uint4(f2tf32(v.x), f2tf32(v.y), f2tf32(v.z), f2tf32(v.w));
    *reinterpret_cast<uint4*>(dst + i) = u;
}

// ======= cp.async multistage GEMM NT: C[M,N] = A[M,K]*B[N,K]^T ===========
// Inputs must already be tf32-rounded f32. BM=BN=128, BK=8, 4 stages,
// 256 threads (8 warps 2x4, warp tile 64x32). smem exactly 48KB.
__global__ void __launch_bounds__(256, 2)
gemm_cp(float* __restrict__ C, const float* __restrict__ A,
        const float* __restrict__ B, int M, int N, int K) {
    __shared__ uint32_t As[4][128][12];
    __shared__ uint32_t Bs[4][128][12];

    int tid = threadIdx.x;
    int m0 = blockIdx.y * 128, n0 = blockIdx.x * 128;
    int wid = tid >> 5, lane = tid & 31;
    int wm = (wid & 1) * 64, wn = (wid >> 1) * 32;
    int qr = lane >> 2, qc = lane & 3;
    int cr = tid >> 1;               // copy row 0..127
    int cc = (tid & 1) * 4;          // copy col 0 or 4 (floats, 16B chunks)

    const float* Asrc = A + (size_t)(m0 + cr) * K + cc;
    const float* Bsrc = B + (size_t)(n0 + cr) * K + cc;

#define COPY_STAGE(s, k0)                                                     \
    do {                                                                      \
        uint32_t da = (uint32_t)__cvta_generic_to_shared(&As[s][cr][cc]);     \
        uint32_t db = (uint32_t)__cvta_generic_to_shared(&Bs[s][cr][cc]);     \
        asm volatile("cp.async.cg.shared.global [%0], [%1], 16;"              \
                     :: "r"(da), "l"(Asrc + (k0)) : "memory");                \
        asm volatile("cp.async.cg.shared.global [%0], [%1], 16;"              \
                     :: "r"(db), "l"(Bsrc + (k0)) : "memory");                \
    } while (0)
#define CP_COMMIT() asm volatile("cp.async.commit_group;" ::: "memory")

    COPY_STAGE(0, 0);  CP_COMMIT();
    COPY_STAGE(1, 8);  CP_COMMIT();
    COPY_STAGE(2, 16); CP_COMMIT();

    float acc[4][4][4] = {};
    int NT = K >> 3;                 // 256 k-tiles of 8
    for (int kt = 0; kt < NT; kt++) {
        int s = kt & 3;
        asm volatile("cp.async.wait_group 2;" ::: "memory");
        __syncthreads();
        int kp = kt + 3;
        if (kp < NT) COPY_STAGE(kp & 3, kp * 8);
        CP_COMMIT();

        uint32_t af[4][4], bf[4][2];
#pragma unroll
        for (int mt = 0; mt < 4; mt++) {
            int m = wm + mt * 16 + qr;
            af[mt][0] = As[s][m][qc];
            af[mt][1] = As[s][m + 8][qc];
            af[mt][2] = As[s][m][qc + 4];
            af[mt][3] = As[s][m + 8][qc + 4];
        }
#pragma unroll
        for (int nt = 0; nt < 4; nt++) {
            int n = wn + nt * 8 + qr;
            bf[nt][0] = Bs[s][n][qc];
            bf[nt][1] = Bs[s][n][qc + 4];
        }
#pragma unroll
        for (int mt = 0; mt < 4; mt++)
#pragma unroll
            for (int nt = 0; nt < 4; nt++)
                mma_tf32(acc[mt][nt], af[mt], bf[nt]);
    }

#pragma unroll
    for (int mt = 0; mt < 4; mt++) {
        int row = m0 + wm + mt * 16 + qr;
#pragma unroll
        for (int nt = 0; nt < 4; nt++) {
            int col = n0 + wn + nt * 8 + qc * 2;
            *reinterpret_cast<float2*>(C + (size_t)row * N + col) =
                make_float2(acc[mt][nt][0], acc[mt][nt][1]);
            *reinterpret_cast<float2*>(C + (size_t)(row + 8) * N + col) =
                make_float2(acc[mt][nt][2], acc[mt][nt][3]);
        }
    }
#undef COPY_STAGE
#undef CP_COMMIT
}

// ---------------- 1) ss = condition @ w_ada^T  (warp per output) ---------
__global__ void ada_kernel(const float* __restrict__ cond,
                           const float* __restrict__ w_ada) {
    int w    = (blockIdx.x * blockDim.x + threadIdx.x) >> 5;
    int lane = threadIdx.x & 31;
    int b = w >> 12;
    int j = w & 4095;
    const float4* c4 = reinterpret_cast<const float4*>(cond + (size_t)b * DC_);
    const float4* w4 = reinterpret_cast<const float4*>(w_ada + (size_t)j * DC_);
    float s = 0.f;
#pragma unroll
    for (int q = 0; q < 16; q++) {
        float4 a  = c4[lane + q * 32];
        float4 bb = w4[lane + q * 32];
        s += a.x * bb.x + a.y * bb.y + a.z * bb.z + a.w * bb.w;
    }
#pragma unroll
    for (int o = 16; o; o >>= 1) s += __shfl_xor_sync(0xffffffffu, s, o);
    if (lane == 0) g_ss[b * 4096 + j] = s;
}

// ------- 2) h = tf32(rmsnorm(x)*(1+scale)+shift) -------------------------
__global__ void rmsada_kernel(const float* __restrict__ x) {
    int row = blockIdx.x;
    int b   = row >> 11;
    int t   = threadIdx.x;
    const float4* xr = reinterpret_cast<const float4*>(x + (size_t)row * D_);
    float4 v0 = xr[t], v1 = xr[t + 256];
    float s = v0.x*v0.x + v0.y*v0.y + v0.z*v0.z + v0.w*v0.w
            + v1.x*v1.x + v1.y*v1.y + v1.z*v1.z + v1.w*v1.w;
    __shared__ float red[256];
    red[t] = s; __syncthreads();
    for (int o = 128; o; o >>= 1) { if (t < o) red[t] += red[t + o]; __syncthreads(); }
    float inv = rsqrtf(red[0] * (1.0f / D_) + EPS);
    const float* shift = g_ss + b * 4096;
    const float* scale = shift + D_;
    uint4* hr = reinterpret_cast<uint4*>(g_h + (size_t)row * D_);
    {
        int d = t * 4;
        float4 sc = *reinterpret_cast<const float4*>(scale + d);
        float4 sh = *reinterpret_cast<const float4*>(shift + d);
        uint4 r;
        r.x = f2tf32(v0.x * inv * (1.f + sc.x) + sh.x);
        r.y = f2tf32(v0.y * inv * (1.f + sc.y) + sh.y);
        r.z = f2tf32(v0.z * inv * (1.f + sc.z) + sh.z);
        r.w = f2tf32(v0.w * inv * (1.f + sc.w) + sh.w);
        hr[t] = r;
    }
    {
        int d = (t + 256) * 4;
        float4 sc = *reinterpret_cast<const float4*>(scale + d);
        float4 sh = *reinterpret_cast<const float4*>(shift + d);
        uint4 r;
        r.x = f2tf32(v1.x * inv * (1.f + sc.x) + sh.x);
        r.y = f2tf32(v1.y * inv * (1.f + sc.y) + sh.y);
        r.z = f2tf32(v1.z * inv * (1.f + sc.z) + sh.z);
        r.w = f2tf32(v1.w * inv * (1.f + sc.w) + sh.w);
        hr[t + 256] = r;
    }
}

// ---------------- 4) per-head rmsnorm + qk_w + RoPE, split q/k/v ---------
__global__ void qkrope_kernel(const float* __restrict__ rope,
                              const float* __restrict__ qkw) {
    int wid  = (blockIdx.x * blockDim.x + threadIdx.x) >> 5;
    int lane = threadIdx.x & 31;
    int b   = wid >> 16;
    int rem = wid & 65535;
    int h   = rem >> 11;
    int l   = rem & 2047;
    size_t rowoff = (size_t)(b * L_ + l) * (3 * D_);
    int col = h * HD_ + lane * 2;
    float2 q = *reinterpret_cast<const float2*>(g_qkv + rowoff + col);
    float2 k = *reinterpret_cast<const float2*>(g_qkv + rowoff + D_ + col);
    float2 v = *reinterpret_cast<const float2*>(g_qkv + rowoff + 2 * D_ + col);
    float sq = q.x * q.x + q.y * q.y;
    float sk = k.x * k.x + k.y * k.y;
#pragma unroll
    for (int o = 16; o; o >>= 1) {
        sq += __shfl_xor_sync(0xffffffffu, sq, o);
        sk += __shfl_xor_sync(0xffffffffu, sk, o);
    }
    float qi = rsqrtf(sq * (1.0f / HD_) + EPS);
    float ki = rsqrtf(sk * (1.0f / HD_) + EPS);
    float2 w2 = *reinterpret_cast<const float2*>(qkw + lane * 2);
    float q0 = q.x * qi * w2.x, q1 = q.y * qi * w2.y;
    float k0 = k.x * ki * w2.x, k1 = k.y * ki * w2.y;
    float2 r0 = *reinterpret_cast<const float2*>(rope + (size_t)l * HD_ + lane * 2);
    float2 r1 = *reinterpret_cast<const float2*>(rope + (size_t)(L_ + l) * HD_ + lane * 2);
    float2 qo, ko;
    qo.x = q0 * r0.x - q1 * r1.x;
    qo.y = q1 * r0.y + q0 * r1.y;
    ko.x = k0 * r0.x - k1 * r1.x;
    ko.y = k1 * r0.y + k0 * r1.y;
    size_t orow = (size_t)wid * HD_ + lane * 2;
    *reinterpret_cast<float2*>(g_q + orow) = qo;
    *reinterpret_cast<float2*>(g_k + orow) = ko;
    *reinterpret_cast<float2*>(g_v + orow) = v;
}

// ============ 5) tensor-core flash attention =============================
__global__ void __launch_bounds__(128, 2) attn_mma() {
    __shared__ uint32_t KQ[64][68];
    __shared__ uint32_t Vs[32][72];
    __shared__ uint32_t Ps[64][36];

    int tid  = threadIdx.x;
    int wid  = tid >> 5, lane = tid & 31;
    int qr   = lane >> 2, qc = lane & 3;
    int bh   = blockIdx.y;
    int bq0  = blockIdx.x * 64;
    int qrow = wid * 16 + qr;

    const float* Qg = g_q + (size_t)bh * L_ * HD_;
    const float* Kg = g_k + (size_t)bh * L_ * HD_;
    const float* Vg = g_v + (size_t)bh * L_ * HD_;

    int pr = tid >> 4;
    int pc = (tid & 15) * 4;
    float4 kp[4], vp[4];
#pragma unroll
    for (int t = 0; t < 4; t++) {
        int r = pr + t * 8;
        kp[t] = *reinterpret_cast<const float4*>(Kg + (size_t)r * HD_ + pc);
        vp[t] = *reinterpret_cast<const float4*>(Vg + (size_t)r * HD_ + pc);
    }

#pragma unroll
    for (int t = 0; t < 8; t++) {
        int idx = tid + t * 128;
        int r = idx >> 4, c = (idx & 15) * 4;
        float4 v = *reinterpret_cast<const float4*>(Qg + (size_t)(bq0 + r) * HD_ + c);
        uint4 u = make_uint4(__float_as_uint(v.x * 0.125f),
                             __float_as_uint(v.y * 0.125f),
                             __float_as_uint(v.z * 0.125f),
                             __float_as_uint(v.w * 0.125f));
        *reinterpret_cast<uint4*>(&KQ[r][c]) = u;
    }
    __syncthreads();

    uint32_t aq[8][4];
#pragma unroll
    for (int kk = 0; kk < 8; kk++) {
        aq[kk][0] = f2tf32(__uint_as_float(KQ[qrow][8 * kk + qc]));
        aq[kk][1] = f2tf32(__uint_as_float(KQ[qrow + 8][8 * kk + qc]));
        aq[kk][2] = f2tf32(__uint_as_float(KQ[qrow][8 * kk + qc + 4]));
        aq[kk][3] = f2tf32(__uint_as_float(KQ[qrow + 8][8 * kk + qc + 4]));
    }

    float o[8][4] = {};
    float m_lo = -INFINITY, m_hi = -INFINITY, l_lo = 0.f, l_hi = 0.f;

    for (int c64 = 0; c64 < 64; c64++) {
        __syncthreads();
#pragma unroll
        for (int t = 0; t < 4; t++) {
            int r = pr + t * 8;
            uint4 uk = make_uint4(f2tf32(kp[t].x), f2tf32(kp[t].y),
                                  f2tf32(kp[t].z), f2tf32(kp[t].w));
            uint4 uv = make_uint4(f2tf32(vp[t].x), f2tf32(vp[t].y),
                                  f2tf32(vp[t].z), f2tf32(vp[t].w));
            *reinterpret_cast<uint4*>(&KQ[r][pc]) = uk;
            *reinterpret_cast<uint4*>(&Vs[r][pc]) = uv;
        }
        __syncthreads();
        if (c64 < 63) {
            size_t koff = (size_t)(c64 + 1) * 32;
#pragma unroll
            for (int t = 0; t < 4; t++) {
                int r = pr + t * 8;
                kp[t] = *reinterpret_cast<const float4*>(Kg + (koff + r) * HD_ + pc);
                vp[t] = *reinterpret_cast<const float4*>(Vg + (koff + r) * HD_ + pc);
            }
        }

        float s[4][4] = {};
#pragma unroll
        for (int kk = 0; kk < 8; kk++) {
#pragma unroll
            for (int j = 0; j < 4; j++) {
                uint32_t bk[2];
                bk[0] = KQ[j * 8 + qr][8 * kk + qc];
                bk[1] = KQ[j * 8 + qr][8 * kk + qc + 4];
                mma_tf32(s[j], aq[kk], bk);
            }
        }

        float mx_lo = -INFINITY, mx_hi = -INFINITY;
#pragma unroll
        for (int j = 0; j < 4; j++) {
            mx_lo = fmaxf(mx_lo, fmaxf(s[j][0], s[j][1]));
            mx_hi = fmaxf(mx_hi, fmaxf(s[j][2], s[j][3]));
        }
        mx_lo = fmaxf(mx_lo, __shfl_xor_sync(0xffffffffu, mx_lo, 1));
        mx_lo = fmaxf(mx_lo, __shfl_xor_sync(0xffffffffu, mx_lo, 2));
        mx_hi = fmaxf(mx_hi, __shfl_xor_sync(0xffffffffu, mx_hi, 1));
        mx_hi = fmaxf(mx_hi, __shfl_xor_sync(0xffffffffu, mx_hi, 2));

        float mn_lo = fmaxf(m_lo, mx_lo);
        float mn_hi = fmaxf(m_hi, mx_hi);
        float cf_lo = __expf(m_lo - mn_lo);
        float cf_hi = __expf(m_hi - mn_hi);
        m_lo = mn_lo; m_hi = mn_hi;

        float ls_lo = 0.f, ls_hi = 0.f;
        uint32_t p[4][4];
#pragma unroll
        for (int j = 0; j < 4; j++) {
            uint32_t u0 = f2tf32(__expf(s[j][0] - mn_lo));
            uint32_t u1 = f2tf32(__expf(s[j][1] - mn_lo));
            uint32_t u2 = f2tf32(__expf(s[j][2] - mn_hi));
            uint32_t u3 = f2tf32(__expf(s[j][3] - mn_hi));
            p[j][0] = u0; p[j][1] = u1; p[j][2] = u2; p[j][3] = u3;
            ls_lo += __uint_as_float(u0) + __uint_as_float(u1);
            ls_hi += __uint_as_float(u2) + __uint_as_float(u3);
        }
        ls_lo += __shfl_xor_sync(0xffffffffu, ls_lo, 1);
        ls_lo += __shfl_xor_sync(0xffffffffu, ls_lo, 2);
        ls_hi += __shfl_xor_sync(0xffffffffu, ls_hi, 1);
        ls_hi += __shfl_xor_sync(0xffffffffu, ls_hi, 2);
        l_lo = l_lo * cf_lo + ls_lo;
        l_hi = l_hi * cf_hi + ls_hi;

#pragma unroll
        for (int n = 0; n < 8; n++) {
            o[n][0] *= cf_lo; o[n][1] *= cf_lo;
            o[n][2] *= cf_hi; o[n][3] *= cf_hi;
        }

#pragma unroll
        for (int j = 0; j < 4; j++) {
            *reinterpret_cast<uint2*>(&Ps[qrow][8 * j + 2 * qc]) =
                make_uint2(p[j][0], p[j][1]);
            *reinterpret_cast<uint2*>(&Ps[qrow + 8][8 * j + 2 * qc]) =
                make_uint2(p[j][2], p[j][3]);
        }
        __syncwarp();

#pragma unroll
        for (int kk2 = 0; kk2 < 4; kk2++) {
            uint32_t ap[4];
            ap[0] = Ps[qrow][8 * kk2 + qc];
            ap[1] = Ps[qrow + 8][8 * kk2 + qc];
            ap[2] = Ps[qrow][8 * kk2 + qc + 4];
            ap[3] = Ps[qrow + 8][8 * kk2 + qc + 4];
#pragma unroll
            for (int n = 0; n < 8; n++) {
                uint32_t bv[2];
                bv[0] = Vs[8 * kk2 + qc][8 * n + qr];
                bv[1] = Vs[8 * kk2 + qc + 4][8 * n + qr];
                mma_tf32(o[n], ap, bv);
            }
        }
        __syncwarp();
    }

    // epilogue: normalize, round to tf32 (feeds out-proj GEMM), store
    int b = bh >> 5, h = bh & 31;
    float inv_lo = 1.f / l_lo, inv_hi = 1.f / l_hi;
    float* base_lo = g_o + (size_t)(b * L_ + bq0 + qrow) * D_ + h * HD_;
    float* base_hi = g_o + (size_t)(b * L_ + bq0 + qrow + 8) * D_ + h * HD_;
#pragma unroll
    for (int n = 0; n < 8; n++) {
        *reinterpret_cast<uint2*>(base_lo + 8 * n + 2 * qc) =
            make_uint2(f2tf32(o[n][0] * inv_lo), f2tf32(o[n][1] * inv_lo));
        *reinterpret_cast<uint2*>(base_hi + 8 * n + 2 * qc) =
            make_uint2(f2tf32(o[n][2] * inv_hi), f2tf32(o[n][3] * inv_hi));
    }
}

// -------------------------------------------------------------------------
extern "C" void kernel_launch(void* const* d_in, const int* in_sizes, int n_in,
                              void* d_out, int out_size) {
    const float* x     = (const float*)d_in[0];
    const float* cond  = (const float*)d_in[1];
    const float* rope  = (const float*)d_in[2];
    const float* w_ada = (const float*)d_in[3];
    const float* w_qkv = (const float*)d_in[4];
    const float* w_out = (const float*)d_in[5];
    const float* qk_w  = (const float*)d_in[6];
    float* out = (float*)d_out;

    void* p;
    cudaGetSymbolAddress(&p, g_h);   float* ph   = (float*)p;
    cudaGetSymbolAddress(&p, g_qkv); float* pqkv = (float*)p;
    cudaGetSymbolAddress(&p, g_o);   float* po   = (float*)p;
    cudaGetSymbolAddress(&p, g_wq);  float* pwq  = (float*)p;
    cudaGetSymbolAddress(&p, g_wo);  float* pwo  = (float*)p;

    cvtw_kernel<<<3 * D_ * D_ / 1024, 256>>>(pwq, w_qkv);
    cvtw_kernel<<<D_ * D_ / 1024, 256>>>(pwo, w_out);
    ada_kernel<<<1024, 256>>>(cond, w_ada);
    rmsada_kernel<<<B_ * L_, 256>>>(x);
    gemm_cp<<<dim3(3 * D_ / 128, B_ * L_ / 128), 256>>>(pqkv, ph, pwq,
                                                        B_ * L_, 3 * D_, D_);
    qkrope_kernel<<<(B_ * NH_ * L_) / 8, 256>>>(rope, qk_w);
    attn_mma<<<dim3(L_ / 64, B_ * NH_), 128>>>();
    gemm_cp<<<dim3(D_ / 128, B_ * L_ / 128), 256>>>(out, po, pwo,
                                                    B_ * L_, D_, D_);
}

// round 6
// speedup vs baseline: 1.1515x; 1.1515x over previous
#include <cuda_runtime.h>
#include <cuda_fp16.h>
#include <math.h>
#include <stdint.h>

#define B_  2
#define L_  2048
#define D_  2048
#define HD_ 64
#define NH_ 32
#define DC_ 2048
#define EPS 1.1920929e-7f

// ---------------- scratch (device globals; no allocation) ----------------
__device__ float  g_ss [B_ * 2 * D_];                  // [b][4096] shift|scale
__device__ float  g_qkv[(size_t)B_ * L_ * 3 * D_];     // qkv rows=(b,l), fp32
__device__ __half g_hh [(size_t)B_ * L_ * D_];         // modulated hidden (fp16)
__device__ __half g_wqh[(size_t)3 * D_ * D_];          // w_qkv fp16
__device__ __half g_woh[(size_t)D_ * D_];              // w_out fp16
__device__ __half g_qh [(size_t)B_ * NH_ * L_ * HD_];  // q (pre-scaled), fp16
__device__ __half g_kh [(size_t)B_ * NH_ * L_ * HD_];
__device__ __half g_vh [(size_t)B_ * NH_ * L_ * HD_];
__device__ __half g_oh [(size_t)B_ * L_ * D_];         // attn out fp16

// ---------------- helpers ------------------------------------------------
__device__ __forceinline__ uint32_t pack_h2(float lo, float hi) {
    uint32_t u;
    asm("cvt.rn.f16x2.f32 %0, %1, %2;" : "=r"(u) : "f"(hi), "f"(lo));
    return u;
}
__device__ __forceinline__ float2 unpack_h2(uint32_t u) {
    __half2 h = *reinterpret_cast<__half2*>(&u);
    return __half22float2(h);
}
__device__ __forceinline__ void mma_f16(float* c, const uint32_t* a,
                                        const uint32_t* b) {
    asm volatile(
        "mma.sync.aligned.m16n8k16.row.col.f32.f16.f16.f32 "
        "{%0,%1,%2,%3}, {%4,%5,%6,%7}, {%8,%9}, {%0,%1,%2,%3};"
        : "+f"(c[0]), "+f"(c[1]), "+f"(c[2]), "+f"(c[3])
        : "r"(a[0]), "r"(a[1]), "r"(a[2]), "r"(a[3]), "r"(b[0]), "r"(b[1]));
}

// ---------------- one-shot weight conversion to fp16 ---------------------
__global__ void cvtw_h(__half* __restrict__ dst, const float* __restrict__ src) {
    int i = (blockIdx.x * 256 + threadIdx.x) * 4;
    float4 v = *reinterpret_cast<const float4*>(src + i);
    uint2 u = make_uint2(pack_h2(v.x, v.y), pack_h2(v.z, v.w));
    *reinterpret_cast<uint2*>(dst + i) = u;
}

// ======= fp16 cp.async GEMM NT: C[M,N] = A[M,K]*B[N,K]^T (fp32 C) ========
// BM=BN=128, BK=16, 4 stages, 256 threads (8 warps 2x4, warp tile 64x32).
// smem rows: 16 halves = 8 words + 4 pad = 12 words (conflict-free frags).
__global__ void __launch_bounds__(256, 2)
gemm_h(float* __restrict__ C, const __half* __restrict__ A,
       const __half* __restrict__ B, int M, int N, int K) {
    __shared__ uint32_t As[4][128][12];
    __shared__ uint32_t Bs[4][128][12];

    int tid = threadIdx.x;
    int m0 = blockIdx.y * 128, n0 = blockIdx.x * 128;
    int wid = tid >> 5, lane = tid & 31;
    int wm = (wid & 1) * 64, wn = (wid >> 1) * 32;
    int qr = lane >> 2, qc = lane & 3;
    int cr = tid >> 1;                // copy row 0..127
    int cw = (tid & 1) * 4;           // dst word 0 or 4 (16B chunks)

    const __half* Asrc = A + (size_t)(m0 + cr) * K + (tid & 1) * 8;
    const __half* Bsrc = B + (size_t)(n0 + cr) * K + (tid & 1) * 8;

#define COPY_STAGE(s, kh)                                                     \
    do {                                                                      \
        uint32_t da = (uint32_t)__cvta_generic_to_shared(&As[s][cr][cw]);     \
        uint32_t db = (uint32_t)__cvta_generic_to_shared(&Bs[s][cr][cw]);     \
        asm volatile("cp.async.cg.shared.global [%0], [%1], 16;"              \
                     :: "r"(da), "l"(Asrc + (kh)) : "memory");                \
        asm volatile("cp.async.cg.shared.global [%0], [%1], 16;"              \
                     :: "r"(db), "l"(Bsrc + (kh)) : "memory");                \
    } while (0)
#define CP_COMMIT() asm volatile("cp.async.commit_group;" ::: "memory")

    COPY_STAGE(0, 0);  CP_COMMIT();
    COPY_STAGE(1, 16); CP_COMMIT();
    COPY_STAGE(2, 32); CP_COMMIT();

    float acc[4][4][4] = {};
    int NT = K >> 4;                  // 128 k-tiles of 16
    for (int kt = 0; kt < NT; kt++) {
        int s = kt & 3;
        asm volatile("cp.async.wait_group 2;" ::: "memory");
        __syncthreads();
        int kp = kt + 3;
        if (kp < NT) COPY_STAGE(kp & 3, kp * 16);
        CP_COMMIT();

        uint32_t af[4][4], bf[4][2];
#pragma unroll
        for (int mt = 0; mt < 4; mt++) {
            int m = wm + mt * 16 + qr;
            af[mt][0] = As[s][m][qc];
            af[mt][1] = As[s][m + 8][qc];
            af[mt][2] = As[s][m][qc + 4];
            af[mt][3] = As[s][m + 8][qc + 4];
        }
#pragma unroll
        for (int nt = 0; nt < 4; nt++) {
            int n = wn + nt * 8 + qr;
            bf[nt][0] = Bs[s][n][qc];
            bf[nt][1] = Bs[s][n][qc + 4];
        }
#pragma unroll
        for (int mt = 0; mt < 4; mt++)
#pragma unroll
            for (int nt = 0; nt < 4; nt++)
                mma_f16(acc[mt][nt], af[mt], bf[nt]);
    }

#pragma unroll
    for (int mt = 0; mt < 4; mt++) {
        int row = m0 + wm + mt * 16 + qr;
#pragma unroll
        for (int nt = 0; nt < 4; nt++) {
            int col = n0 + wn + nt * 8 + qc * 2;
            *reinterpret_cast<float2*>(C + (size_t)row * N + col) =
                make_float2(acc[mt][nt][0], acc[mt][nt][1]);
            *reinterpret_cast<float2*>(C + (size_t)(row + 8) * N + col) =
                make_float2(acc[mt][nt][2], acc[mt][nt][3]);
        }
    }
#undef COPY_STAGE
#undef CP_COMMIT
}

// ---------------- 1) ss = condition @ w_ada^T  (warp per output) ---------
__global__ void ada_kernel(const float* __restrict__ cond,
                           const float* __restrict__ w_ada) {
    int w    = (blockIdx.x * blockDim.x + threadIdx.x) >> 5;
    int lane = threadIdx.x & 31;
    int b = w >> 12;
    int j = w & 4095;
    const float4* c4 = reinterpret_cast<const float4*>(cond + (size_t)b * DC_);
    const float4* w4 = reinterpret_cast<const float4*>(w_ada + (size_t)j * DC_);
    float s = 0.f;
#pragma unroll
    for (int q = 0; q < 16; q++) {
        float4 a  = c4[lane + q * 32];
        float4 bb = w4[lane + q * 32];
        s += a.x * bb.x + a.y * bb.y + a.z * bb.z + a.w * bb.w;
    }
#pragma unroll
    for (int o = 16; o; o >>= 1) s += __shfl_xor_sync(0xffffffffu, s, o);
    if (lane == 0) g_ss[b * 4096 + j] = s;
}

// ------- 2) h = fp16(rmsnorm(x)*(1+scale)+shift) -------------------------
__global__ void rmsada_kernel(const float* __restrict__ x) {
    int row = blockIdx.x;
    int b   = row >> 11;
    int t   = threadIdx.x;
    const float4* xr = reinterpret_cast<const float4*>(x + (size_t)row * D_);
    float4 v0 = xr[t], v1 = xr[t + 256];
    float s = v0.x*v0.x + v0.y*v0.y + v0.z*v0.z + v0.w*v0.w
            + v1.x*v1.x + v1.y*v1.y + v1.z*v1.z + v1.w*v1.w;
    __shared__ float red[256];
    red[t] = s; __syncthreads();
    for (int o = 128; o; o >>= 1) { if (t < o) red[t] += red[t + o]; __syncthreads(); }
    float inv = rsqrtf(red[0] * (1.0f / D_) + EPS);
    const float* shift = g_ss + b * 4096;
    const float* scale = shift + D_;
    uint2* hr = reinterpret_cast<uint2*>(g_hh + (size_t)row * D_);
    {
        int d = t * 4;
        float4 sc = *reinterpret_cast<const float4*>(scale + d);
        float4 sh = *reinterpret_cast<const float4*>(shift + d);
        hr[t] = make_uint2(
            pack_h2(v0.x * inv * (1.f + sc.x) + sh.x,
                    v0.y * inv * (1.f + sc.y) + sh.y),
            pack_h2(v0.z * inv * (1.f + sc.z) + sh.z,
                    v0.w * inv * (1.f + sc.w) + sh.w));
    }
    {
        int d = (t + 256) * 4;
        float4 sc = *reinterpret_cast<const float4*>(scale + d);
        float4 sh = *reinterpret_cast<const float4*>(shift + d);
        hr[t + 256] = make_uint2(
            pack_h2(v1.x * inv * (1.f + sc.x) + sh.x,
                    v1.y * inv * (1.f + sc.y) + sh.y),
            pack_h2(v1.z * inv * (1.f + sc.z) + sh.z,
                    v1.w * inv * (1.f + sc.w) + sh.w));
    }
}

// ------- 4) per-head rmsnorm + qk_w + RoPE -> fp16 q/k/v -----------------
__global__ void qkrope_kernel(const float* __restrict__ rope,
                              const float* __restrict__ qkw) {
    int wid  = (blockIdx.x * blockDim.x + threadIdx.x) >> 5;  // (b*32+h)*2048+l
    int lane = threadIdx.x & 31;
    int b   = wid >> 16;
    int rem = wid & 65535;
    int h   = rem >> 11;
    int l   = rem & 2047;
    size_t rowoff = (size_t)(b * L_ + l) * (3 * D_);
    int col = h * HD_ + lane * 2;
    float2 q = *reinterpret_cast<const float2*>(g_qkv + rowoff + col);
    float2 k = *reinterpret_cast<const float2*>(g_qkv + rowoff + D_ + col);
    float2 v = *reinterpret_cast<const float2*>(g_qkv + rowoff + 2 * D_ + col);
    float sq = q.x * q.x + q.y * q.y;
    float sk = k.x * k.x + k.y * k.y;
#pragma unroll
    for (int o = 16; o; o >>= 1) {
        sq += __shfl_xor_sync(0xffffffffu, sq, o);
        sk += __shfl_xor_sync(0xffffffffu, sk, o);
    }
    float qi = rsqrtf(sq * (1.0f / HD_) + EPS);
    float ki = rsqrtf(sk * (1.0f / HD_) + EPS);
    float2 w2 = *reinterpret_cast<const float2*>(qkw + lane * 2);
    float q0 = q.x * qi * w2.x, q1 = q.y * qi * w2.y;
    float k0 = k.x * ki * w2.x, k1 = k.y * ki * w2.y;
    float2 r0 = *reinterpret_cast<const float2*>(rope + (size_t)l * HD_ + lane * 2);
    float2 r1 = *reinterpret_cast<const float2*>(rope + (size_t)(L_ + l) * HD_ + lane * 2);
    float2 qo, ko;
    qo.x = q0 * r0.x - q1 * r1.x;
    qo.y = q1 * r0.y + q0 * r1.y;
    ko.x = k0 * r0.x - k1 * r1.x;
    ko.y = k1 * r0.y + k0 * r1.y;
    size_t orow = (size_t)wid * HD_ + lane * 2;
    // q pre-scaled by softmax scale 1/sqrt(64)
    *reinterpret_cast<uint32_t*>(g_qh + orow) = pack_h2(qo.x * 0.125f, qo.y * 0.125f);
    *reinterpret_cast<uint32_t*>(g_kh + orow) = pack_h2(ko.x, ko.y);
    *reinterpret_cast<uint32_t*>(g_vh + orow) = pack_h2(v.x, v.y);
}

// ============ 5) fp16 tensor-core flash attention ========================
// BQ=64 (4 warps x 16 rows), BC=32 keys/chunk, m16n8k16 fp16 MMA.
__global__ void __launch_bounds__(128, 2) attn_h() {
    __shared__ uint32_t KQ[64][32];   // Q(64 rows)/K(32 rows): 64-half rows, XOR swizzle
    __shared__ __half   Vt[64][34];   // V transposed: rows=d, 32 l-halves, pad 2
    __shared__ uint32_t Ps[64][20];   // P: 32 halves = 16 words, pad 4

    int tid  = threadIdx.x;
    int wid  = tid >> 5, lane = tid & 31;
    int qr   = lane >> 2, qc = lane & 3;
    int bh   = blockIdx.y;
    int bq0  = blockIdx.x * 64;
    int qrow = wid * 16 + qr;

    const __half* Qg = g_qh + (size_t)bh * L_ * HD_;
    const __half* Kg = g_kh + (size_t)bh * L_ * HD_;
    const __half* Vg = g_vh + (size_t)bh * L_ * HD_;

    // prefetch chunk 0: 32 rows x 64 halves; thread -> (row, 8-half chunk)
    int prA = tid >> 3;               // used with +16 for second iter (rows 0..31)
    int chA = tid & 7;                // 8-half chunk in row
    uint4 kp[2], vp[2];
#pragma unroll
    for (int t = 0; t < 2; t++) {
        int r = prA + t * 16;
        kp[t] = *reinterpret_cast<const uint4*>(Kg + (size_t)r * HD_ + chA * 8);
        vp[t] = *reinterpret_cast<const uint4*>(Vg + (size_t)r * HD_ + chA * 8);
    }

    // stage Q (already scaled): 64 rows x 8 chunks
#pragma unroll
    for (int t = 0; t < 4; t++) {
        int idx = tid + t * 128;
        int r = idx >> 3, ch = idx & 7;
        uint4 u = *reinterpret_cast<const uint4*>(Qg + (size_t)(bq0 + r) * HD_ + ch * 8);
        int pw = (ch * 4) ^ ((r & 7) << 2);
        *reinterpret_cast<uint4*>(&KQ[r][pw]) = u;
    }
    __syncthreads();

    // Q fragments (half2 regs), kept for whole kernel
    uint32_t aq[4][4];
#pragma unroll
    for (int kk = 0; kk < 4; kk++) {
        int w0 = (8 * kk + qc) ^ (qr << 2);
        int w1 = (8 * kk + qc + 4) ^ (qr << 2);
        aq[kk][0] = KQ[qrow][w0];
        aq[kk][1] = KQ[qrow + 8][w0];
        aq[kk][2] = KQ[qrow][w1];
        aq[kk][3] = KQ[qrow + 8][w1];
    }

    float o[8][4] = {};
    float m_lo = -INFINITY, m_hi = -INFINITY, l_lo = 0.f, l_hi = 0.f;

    for (int c64 = 0; c64 < 64; c64++) {
        __syncthreads();              // prior reads of KQ/Vt done
        // store prefetched K chunk (swizzled) + V transposed
#pragma unroll
        for (int t = 0; t < 2; t++) {
            int r = prA + t * 16;
            int pw = (chA * 4) ^ ((r & 7) << 2);
            *reinterpret_cast<uint4*>(&KQ[r][pw]) = kp[t];
            __half vh[8];
            *reinterpret_cast<uint4*>(vh) = vp[t];
#pragma unroll
            for (int i = 0; i < 8; i++) Vt[chA * 8 + i][r] = vh[i];
        }
        __syncthreads();
        // prefetch next chunk
        if (c64 < 63) {
            size_t koff = (size_t)(c64 + 1) * 32;
#pragma unroll
            for (int t = 0; t < 2; t++) {
                int r = prA + t * 16;
                kp[t] = *reinterpret_cast<const uint4*>(Kg + (koff + r) * HD_ + chA * 8);
                vp[t] = *reinterpret_cast<const uint4*>(Vg + (koff + r) * HD_ + chA * 8);
            }
        }

        // ---- S = Q K^T (m16 x n32 per warp): 16 MMAs ----
        float s[4][4] = {};
#pragma unroll
        for (int kk = 0; kk < 4; kk++) {
#pragma unroll
            for (int j = 0; j < 4; j++) {
                int r = j * 8 + qr;
                uint32_t bk[2];
                bk[0] = KQ[r][(8 * kk + qc) ^ (qr << 2)];
                bk[1] = KQ[r][(8 * kk + qc + 4) ^ (qr << 2)];
                mma_f16(s[j], aq[kk], bk);
            }
        }

        // ---- online softmax (fragment layout) ----
        float mx_lo = -INFINITY, mx_hi = -INFINITY;
#pragma unroll
        for (int j = 0; j < 4; j++) {
            mx_lo = fmaxf(mx_lo, fmaxf(s[j][0], s[j][1]));
            mx_hi = fmaxf(mx_hi, fmaxf(s[j][2], s[j][3]));
        }
        mx_lo = fmaxf(mx_lo, __shfl_xor_sync(0xffffffffu, mx_lo, 1));
        mx_lo = fmaxf(mx_lo, __shfl_xor_sync(0xffffffffu, mx_lo, 2));
        mx_hi = fmaxf(mx_hi, __shfl_xor_sync(0xffffffffu, mx_hi, 1));
        mx_hi = fmaxf(mx_hi, __shfl_xor_sync(0xffffffffu, mx_hi, 2));

        float mn_lo = fmaxf(m_lo, mx_lo);
        float mn_hi = fmaxf(m_hi, mx_hi);
        float cf_lo = __expf(m_lo - mn_lo);
        float cf_hi = __expf(m_hi - mn_hi);
        m_lo = mn_lo; m_hi = mn_hi;

        float ls_lo = 0.f, ls_hi = 0.f;
#pragma unroll
        for (int j = 0; j < 4; j++) {
            uint32_t plo = pack_h2(__expf(s[j][0] - mn_lo), __expf(s[j][1] - mn_lo));
            uint32_t phi = pack_h2(__expf(s[j][2] - mn_hi), __expf(s[j][3] - mn_hi));
            Ps[qrow][4 * j + qc]     = plo;
            Ps[qrow + 8][4 * j + qc] = phi;
            float2 flo = unpack_h2(plo), fhi = unpack_h2(phi);
            ls_lo += flo.x + flo.y;   // l from ROUNDED P: num/den errors cancel
            ls_hi += fhi.x + fhi.y;
        }
        ls_lo += __shfl_xor_sync(0xffffffffu, ls_lo, 1);
        ls_lo += __shfl_xor_sync(0xffffffffu, ls_lo, 2);
        ls_hi += __shfl_xor_sync(0xffffffffu, ls_hi, 1);
        ls_hi += __shfl_xor_sync(0xffffffffu, ls_hi, 2);
        l_lo = l_lo * cf_lo + ls_lo;
        l_hi = l_hi * cf_hi + ls_hi;

#pragma unroll
        for (int n = 0; n < 8; n++) {
            o[n][0] *= cf_lo; o[n][1] *= cf_lo;
            o[n][2] *= cf_hi; o[n][3] *= cf_hi;
        }
        __syncwarp();

        // ---- O += P V : 16 MMAs ----
#pragma unroll
        for (int kk2 = 0; kk2 < 2; kk2++) {
            uint32_t ap[4];
            ap[0] = Ps[qrow][8 * kk2 + qc];
            ap[1] = Ps[qrow + 8][8 * kk2 + qc];
            ap[2] = Ps[qrow][8 * kk2 + qc + 4];
            ap[3] = Ps[qrow + 8][8 * kk2 + qc + 4];
#pragma unroll
            for (int n = 0; n < 8; n++) {
                int vr = 8 * n + qr;
                uint32_t bv[2];
                bv[0] = *reinterpret_cast<const uint32_t*>(&Vt[vr][2 * (8 * kk2 + qc)]);
                bv[1] = *reinterpret_cast<const uint32_t*>(&Vt[vr][2 * (8 * kk2 + qc + 4)]);
                mma_f16(o[n], ap, bv);
            }
        }
        __syncwarp();
    }

    // epilogue: normalize, fp16, store to g_oh rows=(b,l), cols=(h,d)
    int b = bh >> 5, h = bh & 31;
    float inv_lo = 1.f / l_lo, inv_hi = 1.f / l_hi;
    __half* base_lo = g_oh + (size_t)(b * L_ + bq0 + qrow) * D_ + h * HD_;
    __half* base_hi = g_oh + (size_t)(b * L_ + bq0 + qrow + 8) * D_ + h * HD_;
#pragma unroll
    for (int n = 0; n < 8; n++) {
        *reinterpret_cast<uint32_t*>(base_lo + 8 * n + 2 * qc) =
            pack_h2(o[n][0] * inv_lo, o[n][1] * inv_lo);
        *reinterpret_cast<uint32_t*>(base_hi + 8 * n + 2 * qc) =
            pack_h2(o[n][2] * inv_hi, o[n][3] * inv_hi);
    }
}

// -------------------------------------------------------------------------
extern "C" void kernel_launch(void* const* d_in, const int* in_sizes, int n_in,
                              void* d_out, int out_size) {
    const float* x     = (const float*)d_in[0];
    const float* cond  = (const float*)d_in[1];
    const float* rope  = (const float*)d_in[2];
    const float* w_ada = (const float*)d_in[3];
    const float* w_qkv = (const float*)d_in[4];
    const float* w_out = (const float*)d_in[5];
    const float* qk_w  = (const float*)d_in[6];
    float* out = (float*)d_out;

    void* p;
    cudaGetSymbolAddress(&p, g_qkv); float*  pqkv = (float*)p;
    cudaGetSymbolAddress(&p, g_hh);  __half* phh  = (__half*)p;
    cudaGetSymbolAddress(&p, g_wqh); __half* pwq  = (__half*)p;
    cudaGetSymbolAddress(&p, g_woh); __half* pwo  = (__half*)p;
    cudaGetSymbolAddress(&p, g_oh);  __half* poh  = (__half*)p;

    cvtw_h<<<3 * D_ * D_ / 1024, 256>>>(pwq, w_qkv);
    cvtw_h<<<D_ * D_ / 1024, 256>>>(pwo, w_out);
    ada_kernel<<<1024, 256>>>(cond, w_ada);
    rmsada_kernel<<<B_ * L_, 256>>>(x);
    gemm_h<<<dim3(3 * D_ / 128, B_ * L_ / 128), 256>>>(pqkv, phh, pwq,
                                                       B_ * L_, 3 * D_, D_);
    qkrope_kernel<<<(B_ * NH_ * L_) / 8, 256>>>(rope, qk_w);
    attn_h<<<dim3(L_ / 64, B_ * NH_), 128>>>();
    gemm_h<<<dim3(D_ / 128, B_ * L_ / 128), 256>>>(out, poh, pwo,
                                                   B_ * L_, D_, D_);
}

// round 7
// speedup vs baseline: 1.4486x; 1.2580x over previous
#include <cuda_runtime.h>
#include <cuda_fp16.h>
#include <math.h>
#include <stdint.h>

#define B_  2
#define L_  2048
#define D_  2048
#define HD_ 64
#define NH_ 32
#define DC_ 2048
#define EPS 1.1920929e-7f

// ---------------- scratch (device globals; no allocation) ----------------
__device__ float  g_ss [B_ * 2 * D_];                  // [b][4096] shift|scale
__device__ float  g_qkv[(size_t)B_ * L_ * 3 * D_];     // qkv rows=(b,l), fp32
__device__ __half g_hh [(size_t)B_ * L_ * D_];         // modulated hidden (fp16)
__device__ __half g_wqh[(size_t)3 * D_ * D_];          // w_qkv fp16
__device__ __half g_woh[(size_t)D_ * D_];              // w_out fp16
__device__ __half g_qh [(size_t)B_ * NH_ * L_ * HD_];  // q (pre-scaled), fp16
__device__ __half g_kh [(size_t)B_ * NH_ * L_ * HD_];
__device__ __half g_vh [(size_t)B_ * NH_ * L_ * HD_];
__device__ __half g_oh [(size_t)B_ * L_ * D_];         // attn out fp16

// ---------------- helpers ------------------------------------------------
__device__ __forceinline__ uint32_t pack_h2(float lo, float hi) {
    uint32_t u;
    asm("cvt.rn.f16x2.f32 %0, %1, %2;" : "=r"(u) : "f"(hi), "f"(lo));
    return u;
}
__device__ __forceinline__ float2 unpack_h2(uint32_t u) {
    __half2 h = *reinterpret_cast<__half2*>(&u);
    return __half22float2(h);
}
__device__ __forceinline__ void mma_f16(float* c, const uint32_t* a,
                                        const uint32_t* b) {
    asm volatile(
        "mma.sync.aligned.m16n8k16.row.col.f32.f16.f16.f32 "
        "{%0,%1,%2,%3}, {%4,%5,%6,%7}, {%8,%9}, {%0,%1,%2,%3};"
        : "+f"(c[0]), "+f"(c[1]), "+f"(c[2]), "+f"(c[3])
        : "r"(a[0]), "r"(a[1]), "r"(a[2]), "r"(a[3]), "r"(b[0]), "r"(b[1]));
}
#define LDSM_X4(r0, r1, r2, r3, addr)                                         \
    asm volatile("ldmatrix.sync.aligned.m8n8.x4.shared.b16 {%0,%1,%2,%3}, [%4];" \
        : "=r"(r0), "=r"(r1), "=r"(r2), "=r"(r3) : "r"(addr))

// ---------------- one-shot weight conversion to fp16 ---------------------
__global__ void cvtw_h(__half* __restrict__ dst, const float* __restrict__ src) {
    int i = (blockIdx.x * 256 + threadIdx.x) * 4;
    float4 v = *reinterpret_cast<const float4*>(src + i);
    uint2 u = make_uint2(pack_h2(v.x, v.y), pack_h2(v.z, v.w));
    *reinterpret_cast<uint2*>(dst + i) = u;
}

// ======= fp16 ldmatrix GEMM NT: C[M,N] = A[M,K]*B[N,K]^T (fp32 C) ========
// BM=BN=128, BK=32, 3 stages (48KB), 256 threads, warp tile 64x32.
// Rows: 32 halves = 16 words; chunk c (16B) of row r at word r*16+4*(c^((r>>1)&3)).
__global__ void __launch_bounds__(256, 2)
gemm_h(float* __restrict__ C, const __half* __restrict__ A,
       const __half* __restrict__ B, int M, int N, int K) {
    __shared__ uint32_t As[3][128][16];
    __shared__ uint32_t Bs[3][128][16];

    int tid = threadIdx.x;
    int m0 = blockIdx.y * 128, n0 = blockIdx.x * 128;
    int wid = tid >> 5, lane = tid & 31;
    int wm = (wid & 1) * 64, wn = (wid >> 1) * 32;
    int qr = lane >> 2, qc = lane & 3;
    int i8 = lane & 7, g = lane >> 3;

    // copy mapping: chunk ids tid, tid+256 -> (row, c)
    int cr = tid >> 2, cc = tid & 3;
    int cw  = 4 * (cc ^ ((cr >> 1) & 3));                 // dst word, row cr
    int cw2 = 4 * (cc ^ (((cr + 64) >> 1) & 3));          // dst word, row cr+64
    const __half* Asrc0 = A + (size_t)(m0 + cr) * K + cc * 8;
    const __half* Asrc1 = A + (size_t)(m0 + cr + 64) * K + cc * 8;
    const __half* Bsrc0 = B + (size_t)(n0 + cr) * K + cc * 8;
    const __half* Bsrc1 = B + (size_t)(n0 + cr + 64) * K + cc * 8;

    uint32_t sA = (uint32_t)__cvta_generic_to_shared(&As[0][0][0]);
    uint32_t sB = (uint32_t)__cvta_generic_to_shared(&Bs[0][0][0]);

#define COPY_STAGE(s, kh)                                                     \
    do {                                                                      \
        uint32_t o1 = (s) * 8192 + (cr * 16) * 4;                             \
        uint32_t o2 = (s) * 8192 + ((cr + 64) * 16) * 4;                      \
        asm volatile("cp.async.cg.shared.global [%0], [%1], 16;"              \
                     :: "r"(sA + o1 + cw * 4), "l"(Asrc0 + (kh)) : "memory"); \
        asm volatile("cp.async.cg.shared.global [%0], [%1], 16;"              \
                     :: "r"(sA + o2 + cw2 * 4), "l"(Asrc1 + (kh)) : "memory");\
        asm volatile("cp.async.cg.shared.global [%0], [%1], 16;"              \
                     :: "r"(sB + o1 + cw * 4), "l"(Bsrc0 + (kh)) : "memory"); \
        asm volatile("cp.async.cg.shared.global [%0], [%1], 16;"              \
                     :: "r"(sB + o2 + cw2 * 4), "l"(Bsrc1 + (kh)) : "memory");\
    } while (0)
#define CP_COMMIT() asm volatile("cp.async.commit_group;" ::: "memory")

    COPY_STAGE(0, 0);  CP_COMMIT();
    COPY_STAGE(1, 32); CP_COMMIT();

    // ldmatrix lane->row/chunk mapping (fixed per thread)
    int arow = wm + i8 + (g & 1) * 8;       // + mt*16
    int acg  = g >> 1;                      // chunk group 0/1
    int brow = wn + i8 + (g >> 1) * 8;      // + nt2*16
    int bcg  = g & 1;

    float acc[4][4][4] = {};
    int NT = K >> 5;                        // 64 k-tiles of 32
    for (int kt = 0; kt < NT; kt++) {
        int s = kt % 3;
        asm volatile("cp.async.wait_group 1;" ::: "memory");
        __syncthreads();
        int kp = kt + 2;
        if (kp < NT) COPY_STAGE(kp % 3, kp * 32);
        CP_COMMIT();

        uint32_t stoff = s * 8192;
#pragma unroll
        for (int kc = 0; kc < 2; kc++) {
            uint32_t af[4][4], bf[4][2];
#pragma unroll
            for (int mt = 0; mt < 4; mt++) {
                int r = arow + mt * 16;
                int w = r * 16 + 4 * ((2 * kc + acg) ^ ((r >> 1) & 3));
                LDSM_X4(af[mt][0], af[mt][1], af[mt][2], af[mt][3],
                        sA + stoff + w * 4);
            }
#pragma unroll
            for (int nt2 = 0; nt2 < 2; nt2++) {
                int r = brow + nt2 * 16;
                int w = r * 16 + 4 * ((2 * kc + bcg) ^ ((r >> 1) & 3));
                LDSM_X4(bf[nt2 * 2][0], bf[nt2 * 2][1],
                        bf[nt2 * 2 + 1][0], bf[nt2 * 2 + 1][1],
                        sB + stoff + w * 4);
            }
#pragma unroll
            for (int mt = 0; mt < 4; mt++)
#pragma unroll
                for (int nt = 0; nt < 4; nt++)
                    mma_f16(acc[mt][nt], af[mt], bf[nt]);
        }
    }

#pragma unroll
    for (int mt = 0; mt < 4; mt++) {
        int row = m0 + wm + mt * 16 + qr;
#pragma unroll
        for (int nt = 0; nt < 4; nt++) {
            int col = n0 + wn + nt * 8 + qc * 2;
            *reinterpret_cast<float2*>(C + (size_t)row * N + col) =
                make_float2(acc[mt][nt][0], acc[mt][nt][1]);
            *reinterpret_cast<float2*>(C + (size_t)(row + 8) * N + col) =
                make_float2(acc[mt][nt][2], acc[mt][nt][3]);
        }
    }
#undef COPY_STAGE
#undef CP_COMMIT
}

// ---------------- 1) ss = condition @ w_ada^T  (warp per output) ---------
__global__ void ada_kernel(const float* __restrict__ cond,
                           const float* __restrict__ w_ada) {
    int w    = (blockIdx.x * blockDim.x + threadIdx.x) >> 5;
    int lane = threadIdx.x & 31;
    int b = w >> 12;
    int j = w & 4095;
    const float4* c4 = reinterpret_cast<const float4*>(cond + (size_t)b * DC_);
    const float4* w4 = reinterpret_cast<const float4*>(w_ada + (size_t)j * DC_);
    float s = 0.f;
#pragma unroll
    for (int q = 0; q < 16; q++) {
        float4 a  = c4[lane + q * 32];
        float4 bb = w4[lane + q * 32];
        s += a.x * bb.x + a.y * bb.y + a.z * bb.z + a.w * bb.w;
    }
#pragma unroll
    for (int o = 16; o; o >>= 1) s += __shfl_xor_sync(0xffffffffu, s, o);
    if (lane == 0) g_ss[b * 4096 + j] = s;
}

// ------- 2) h = fp16(rmsnorm(x)*(1+scale)+shift) -------------------------
__global__ void rmsada_kernel(const float* __restrict__ x) {
    int row = blockIdx.x;
    int b   = row >> 11;
    int t   = threadIdx.x;
    const float4* xr = reinterpret_cast<const float4*>(x + (size_t)row * D_);
    float4 v0 = xr[t], v1 = xr[t + 256];
    float s = v0.x*v0.x + v0.y*v0.y + v0.z*v0.z + v0.w*v0.w
            + v1.x*v1.x + v1.y*v1.y + v1.z*v1.z + v1.w*v1.w;
    __shared__ float red[256];
    red[t] = s; __syncthreads();
    for (int o = 128; o; o >>= 1) { if (t < o) red[t] += red[t + o]; __syncthreads(); }
    float inv = rsqrtf(red[0] * (1.0f / D_) + EPS);
    const float* shift = g_ss + b * 4096;
    const float* scale = shift + D_;
    uint2* hr = reinterpret_cast<uint2*>(g_hh + (size_t)row * D_);
    {
        int d = t * 4;
        float4 sc = *reinterpret_cast<const float4*>(scale + d);
        float4 sh = *reinterpret_cast<const float4*>(shift + d);
        hr[t] = make_uint2(
            pack_h2(v0.x * inv * (1.f + sc.x) + sh.x,
                    v0.y * inv * (1.f + sc.y) + sh.y),
            pack_h2(v0.z * inv * (1.f + sc.z) + sh.z,
                    v0.w * inv * (1.f + sc.w) + sh.w));
    }
    {
        int d = (t + 256) * 4;
        float4 sc = *reinterpret_cast<const float4*>(scale + d);
        float4 sh = *reinterpret_cast<const float4*>(shift + d);
        hr[t + 256] = make_uint2(
            pack_h2(v1.x * inv * (1.f + sc.x) + sh.x,
                    v1.y * inv * (1.f + sc.y) + sh.y),
            pack_h2(v1.z * inv * (1.f + sc.z) + sh.z,
                    v1.w * inv * (1.f + sc.w) + sh.w));
    }
}

// ------- 4) per-head rmsnorm + qk_w + RoPE -> fp16 q/k/v -----------------
__global__ void qkrope_kernel(const float* __restrict__ rope,
                              const float* __restrict__ qkw) {
    int wid  = (blockIdx.x * blockDim.x + threadIdx.x) >> 5;  // (b*32+h)*2048+l
    int lane = threadIdx.x & 31;
    int b   = wid >> 16;
    int rem = wid & 65535;
    int h   = rem >> 11;
    int l   = rem & 2047;
    size_t rowoff = (size_t)(b * L_ + l) * (3 * D_);
    int col = h * HD_ + lane * 2;
    float2 q = *reinterpret_cast<const float2*>(g_qkv + rowoff + col);
    float2 k = *reinterpret_cast<const float2*>(g_qkv + rowoff + D_ + col);
    float2 v = *reinterpret_cast<const float2*>(g_qkv + rowoff + 2 * D_ + col);
    float sq = q.x * q.x + q.y * q.y;
    float sk = k.x * k.x + k.y * k.y;
#pragma unroll
    for (int o = 16; o; o >>= 1) {
        sq += __shfl_xor_sync(0xffffffffu, sq, o);
        sk += __shfl_xor_sync(0xffffffffu, sk, o);
    }
    float qi = rsqrtf(sq * (1.0f / HD_) + EPS);
    float ki = rsqrtf(sk * (1.0f / HD_) + EPS);
    float2 w2 = *reinterpret_cast<const float2*>(qkw + lane * 2);
    float q0 = q.x * qi * w2.x, q1 = q.y * qi * w2.y;
    float k0 = k.x * ki * w2.x, k1 = k.y * ki * w2.y;
    float2 r0 = *reinterpret_cast<const float2*>(rope + (size_t)l * HD_ + lane * 2);
    float2 r1 = *reinterpret_cast<const float2*>(rope + (size_t)(L_ + l) * HD_ + lane * 2);
    float2 qo, ko;
    qo.x = q0 * r0.x - q1 * r1.x;
    qo.y = q1 * r0.y + q0 * r1.y;
    ko.x = k0 * r0.x - k1 * r1.x;
    ko.y = k1 * r0.y + k0 * r1.y;
    size_t orow = (size_t)wid * HD_ + lane * 2;
    *reinterpret_cast<uint32_t*>(g_qh + orow) = pack_h2(qo.x * 0.125f, qo.y * 0.125f);
    *reinterpret_cast<uint32_t*>(g_kh + orow) = pack_h2(ko.x, ko.y);
    *reinterpret_cast<uint32_t*>(g_vh + orow) = pack_h2(v.x, v.y);
}

// ============ 5) fp16 tensor-core flash attention ========================
__global__ void __launch_bounds__(128, 2) attn_h() {
    __shared__ uint32_t KQ[64][32];
    __shared__ __half   Vt[64][34];
    __shared__ uint32_t Ps[64][20];

    int tid  = threadIdx.x;
    int wid  = tid >> 5, lane = tid & 31;
    int qr   = lane >> 2, qc = lane & 3;
    int bh   = blockIdx.y;
    int bq0  = blockIdx.x * 64;
    int qrow = wid * 16 + qr;

    const __half* Qg = g_qh + (size_t)bh * L_ * HD_;
    const __half* Kg = g_kh + (size_t)bh * L_ * HD_;
    const __half* Vg = g_vh + (size_t)bh * L_ * HD_;

    int prA = tid >> 3;
    int chA = tid & 7;
    uint4 kp[2], vp[2];
#pragma unroll
    for (int t = 0; t < 2; t++) {
        int r = prA + t * 16;
        kp[t] = *reinterpret_cast<const uint4*>(Kg + (size_t)r * HD_ + chA * 8);
        vp[t] = *reinterpret_cast<const uint4*>(Vg + (size_t)r * HD_ + chA * 8);
    }

#pragma unroll
    for (int t = 0; t < 4; t++) {
        int idx = tid + t * 128;
        int r = idx >> 3, ch = idx & 7;
        uint4 u = *reinterpret_cast<const uint4*>(Qg + (size_t)(bq0 + r) * HD_ + ch * 8);
        int pw = (ch * 4) ^ ((r & 7) << 2);
        *reinterpret_cast<uint4*>(&KQ[r][pw]) = u;
    }
    __syncthreads();

    uint32_t aq[4][4];
#pragma unroll
    for (int kk = 0; kk < 4; kk++) {
        int w0 = (8 * kk + qc) ^ (qr << 2);
        int w1 = (8 * kk + qc + 4) ^ (qr << 2);
        aq[kk][0] = KQ[qrow][w0];
        aq[kk][1] = KQ[qrow + 8][w0];
        aq[kk][2] = KQ[qrow][w1];
        aq[kk][3] = KQ[qrow + 8][w1];
    }

    float o[8][4] = {};
    float m_lo = -INFINITY, m_hi = -INFINITY, l_lo = 0.f, l_hi = 0.f;

    for (int c64 = 0; c64 < 64; c64++) {
        __syncthreads();
#pragma unroll
        for (int t = 0; t < 2; t++) {
            int r = prA + t * 16;
            int pw = (chA * 4) ^ ((r & 7) << 2);
            *reinterpret_cast<uint4*>(&KQ[r][pw]) = kp[t];
            __half vh[8];
            *reinterpret_cast<uint4*>(vh) = vp[t];
#pragma unroll
            for (int i = 0; i < 8; i++) Vt[chA * 8 + i][r] = vh[i];
        }
        __syncthreads();
        if (c64 < 63) {
            size_t koff = (size_t)(c64 + 1) * 32;
#pragma unroll
            for (int t = 0; t < 2; t++) {
                int r = prA + t * 16;
                kp[t] = *reinterpret_cast<const uint4*>(Kg + (koff + r) * HD_ + chA * 8);
                vp[t] = *reinterpret_cast<const uint4*>(Vg + (koff + r) * HD_ + chA * 8);
            }
        }

        float s[4][4] = {};
#pragma unroll
        for (int kk = 0; kk < 4; kk++) {
#pragma unroll
            for (int j = 0; j < 4; j++) {
                int r = j * 8 + qr;
                uint32_t bk[2];
                bk[0] = KQ[r][(8 * kk + qc) ^ (qr << 2)];
                bk[1] = KQ[r][(8 * kk + qc + 4) ^ (qr << 2)];
                mma_f16(s[j], aq[kk], bk);
            }
        }

        float mx_lo = -INFINITY, mx_hi = -INFINITY;
#pragma unroll
        for (int j = 0; j < 4; j++) {
            mx_lo = fmaxf(mx_lo, fmaxf(s[j][0], s[j][1]));
            mx_hi = fmaxf(mx_hi, fmaxf(s[j][2], s[j][3]));
        }
        mx_lo = fmaxf(mx_lo, __shfl_xor_sync(0xffffffffu, mx_lo, 1));
        mx_lo = fmaxf(mx_lo, __shfl_xor_sync(0xffffffffu, mx_lo, 2));
        mx_hi = fmaxf(mx_hi, __shfl_xor_sync(0xffffffffu, mx_hi, 1));
        mx_hi = fmaxf(mx_hi, __shfl_xor_sync(0xffffffffu, mx_hi, 2));

        float mn_lo = fmaxf(m_lo, mx_lo);
        float mn_hi = fmaxf(m_hi, mx_hi);
        float cf_lo = __expf(m_lo - mn_lo);
        float cf_hi = __expf(m_hi - mn_hi);
        m_lo = mn_lo; m_hi = mn_hi;

        float ls_lo = 0.f, ls_hi = 0.f;
#pragma unroll
        for (int j = 0; j < 4; j++) {
            uint32_t plo = pack_h2(__expf(s[j][0] - mn_lo), __expf(s[j][1] - mn_lo));
            uint32_t phi = pack_h2(__expf(s[j][2] - mn_hi), __expf(s[j][3] - mn_hi));
            Ps[qrow][4 * j + qc]     = plo;
            Ps[qrow + 8][4 * j + qc] = phi;
            float2 flo = unpack_h2(plo), fhi = unpack_h2(phi);
            ls_lo += flo.x + flo.y;
            ls_hi += fhi.x + fhi.y;
        }
        ls_lo += __shfl_xor_sync(0xffffffffu, ls_lo, 1);
        ls_lo += __shfl_xor_sync(0xffffffffu, ls_lo, 2);
        ls_hi += __shfl_xor_sync(0xffffffffu, ls_hi, 1);
        ls_hi += __shfl_xor_sync(0xffffffffu, ls_hi, 2);
        l_lo = l_lo * cf_lo + ls_lo;
        l_hi = l_hi * cf_hi + ls_hi;

#pragma unroll
        for (int n = 0; n < 8; n++) {
            o[n][0] *= cf_lo; o[n][1] *= cf_lo;
            o[n][2] *= cf_hi; o[n][3] *= cf_hi;
        }
        __syncwarp();

#pragma unroll
        for (int kk2 = 0; kk2 < 2; kk2++) {
            uint32_t ap[4];
            ap[0] = Ps[qrow][8 * kk2 + qc];
            ap[1] = Ps[qrow + 8][8 * kk2 + qc];
            ap[2] = Ps[qrow][8 * kk2 + qc + 4];
            ap[3] = Ps[qrow + 8][8 * kk2 + qc + 4];
#pragma unroll
            for (int n = 0; n < 8; n++) {
                int vr = 8 * n + qr;
                uint32_t bv[2];
                bv[0] = *reinterpret_cast<const uint32_t*>(&Vt[vr][2 * (8 * kk2 + qc)]);
                bv[1] = *reinterpret_cast<const uint32_t*>(&Vt[vr][2 * (8 * kk2 + qc + 4)]);
                mma_f16(o[n], ap, bv);
            }
        }
        __syncwarp();
    }

    int b = bh >> 5, h = bh & 31;
    float inv_lo = 1.f / l_lo, inv_hi = 1.f / l_hi;
    __half* base_lo = g_oh + (size_t)(b * L_ + bq0 + qrow) * D_ + h * HD_;
    __half* base_hi = g_oh + (size_t)(b * L_ + bq0 + qrow + 8) * D_ + h * HD_;
#pragma unroll
    for (int n = 0; n < 8; n++) {
        *reinterpret_cast<uint32_t*>(base_lo + 8 * n + 2 * qc) =
            pack_h2(o[n][0] * inv_lo, o[n][1] * inv_lo);
        *reinterpret_cast<uint32_t*>(base_hi + 8 * n + 2 * qc) =
            pack_h2(o[n][2] * inv_hi, o[n][3] * inv_hi);
    }
}

// -------------------------------------------------------------------------
extern "C" void kernel_launch(void* const* d_in, const int* in_sizes, int n_in,
                              void* d_out, int out_size) {
    const float* x     = (const float*)d_in[0];
    const float* cond  = (const float*)d_in[1];
    const float* rope  = (const float*)d_in[2];
    const float* w_ada = (const float*)d_in[3];
    const float* w_qkv = (const float*)d_in[4];
    const float* w_out = (const float*)d_in[5];
    const float* qk_w  = (const float*)d_in[6];
    float* out = (float*)d_out;

    void* p;
    cudaGetSymbolAddress(&p, g_qkv); float*  pqkv = (float*)p;
    cudaGetSymbolAddress(&p, g_hh);  __half* phh  = (__half*)p;
    cudaGetSymbolAddress(&p, g_wqh); __half* pwq  = (__half*)p;
    cudaGetSymbolAddress(&p, g_woh); __half* pwo  = (__half*)p;
    cudaGetSymbolAddress(&p, g_oh);  __half* poh  = (__half*)p;

    cvtw_h<<<3 * D_ * D_ / 1024, 256>>>(pwq, w_qkv);
    cvtw_h<<<D_ * D_ / 1024, 256>>>(pwo, w_out);
    ada_kernel<<<1024, 256>>>(cond, w_ada);
    rmsada_kernel<<<B_ * L_, 256>>>(x);
    gemm_h<<<dim3(3 * D_ / 128, B_ * L_ / 128), 256>>>(pqkv, phh, pwq,
                                                       B_ * L_, 3 * D_, D_);
    qkrope_kernel<<<(B_ * NH_ * L_) / 8, 256>>>(rope, qk_w);
    attn_h<<<dim3(L_ / 64, B_ * NH_), 128>>>();
    gemm_h<<<dim3(D_ / 128, B_ * L_ / 128), 256>>>(out, poh, pwo,
                                                   B_ * L_, D_, D_);
}

// round 8
// speedup vs baseline: 2.4006x; 1.6572x over previous
#include <cuda_runtime.h>
#include <cuda_fp16.h>
#include <math.h>
#include <stdint.h>

#define B_  2
#define L_  2048
#define D_  2048
#define HD_ 64
#define NH_ 32
#define DC_ 2048
#define EPS 1.1920929e-7f

// ---------------- scratch (device globals; no allocation) ----------------
__device__ float  g_ss [B_ * 2 * D_];                  // [b][4096] shift|scale
__device__ float  g_qkv[(size_t)B_ * L_ * 3 * D_];     // qkv rows=(b,l), fp32
__device__ __half g_hh [(size_t)B_ * L_ * D_];         // modulated hidden (fp16)
__device__ __half g_wqh[(size_t)3 * D_ * D_];          // w_qkv fp16
__device__ __half g_woh[(size_t)D_ * D_];              // w_out fp16
__device__ __half g_qh [(size_t)B_ * NH_ * L_ * HD_];  // q (pre-scaled), fp16
__device__ __half g_kh [(size_t)B_ * NH_ * L_ * HD_];
__device__ __half g_vh [(size_t)B_ * NH_ * L_ * HD_];
__device__ __half g_oh [(size_t)B_ * L_ * D_];         // attn out fp16

// ---------------- helpers ------------------------------------------------
__device__ __forceinline__ uint32_t pack_h2(float lo, float hi) {
    uint32_t u;
    asm("cvt.rn.f16x2.f32 %0, %1, %2;" : "=r"(u) : "f"(hi), "f"(lo));
    return u;
}
__device__ __forceinline__ float2 unpack_h2(uint32_t u) {
    __half2 h = *reinterpret_cast<__half2*>(&u);
    return __half22float2(h);
}
__device__ __forceinline__ void mma_f16(float* c, const uint32_t* a,
                                        const uint32_t* b) {
    asm volatile(
        "mma.sync.aligned.m16n8k16.row.col.f32.f16.f16.f32 "
        "{%0,%1,%2,%3}, {%4,%5,%6,%7}, {%8,%9}, {%0,%1,%2,%3};"
        : "+f"(c[0]), "+f"(c[1]), "+f"(c[2]), "+f"(c[3])
        : "r"(a[0]), "r"(a[1]), "r"(a[2]), "r"(a[3]), "r"(b[0]), "r"(b[1]));
}
#define LDSM_X4(r0, r1, r2, r3, addr)                                         \
    asm volatile("ldmatrix.sync.aligned.m8n8.x4.shared.b16 {%0,%1,%2,%3}, [%4];" \
        : "=r"(r0), "=r"(r1), "=r"(r2), "=r"(r3) : "r"(addr))

// ---------------- one-shot weight conversion to fp16 ---------------------
__global__ void cvtw_h(__half* __restrict__ dst, const float* __restrict__ src) {
    int i = (blockIdx.x * 256 + threadIdx.x) * 4;
    float4 v = *reinterpret_cast<const float4*>(src + i);
    uint2 u = make_uint2(pack_h2(v.x, v.y), pack_h2(v.z, v.w));
    *reinterpret_cast<uint2*>(dst + i) = u;
}

// ======= fp16 ldmatrix GEMM NT: C[M,N] = A[M,K]*B[N,K]^T (fp32 C) ========
// BM=BN=128, BK=32, 3 stages (48KB), 256 threads, warp tile 64x32.
__global__ void __launch_bounds__(256, 2)
gemm_h(float* __restrict__ C, const __half* __restrict__ A,
       const __half* __restrict__ B, int M, int N, int K) {
    __shared__ uint32_t As[3][128][16];
    __shared__ uint32_t Bs[3][128][16];

    int tid = threadIdx.x;
    int m0 = blockIdx.y * 128, n0 = blockIdx.x * 128;
    int wid = tid >> 5, lane = tid & 31;
    int wm = (wid & 1) * 64, wn = (wid >> 1) * 32;
    int qr = lane >> 2, qc = lane & 3;
    int i8 = lane & 7, g = lane >> 3;

    int cr = tid >> 2, cc = tid & 3;
    int cw  = 4 * (cc ^ ((cr >> 1) & 3));
    int cw2 = 4 * (cc ^ (((cr + 64) >> 1) & 3));
    const __half* Asrc0 = A + (size_t)(m0 + cr) * K + cc * 8;
    const __half* Asrc1 = A + (size_t)(m0 + cr + 64) * K + cc * 8;
    const __half* Bsrc0 = B + (size_t)(n0 + cr) * K + cc * 8;
    const __half* Bsrc1 = B + (size_t)(n0 + cr + 64) * K + cc * 8;

    uint32_t sA = (uint32_t)__cvta_generic_to_shared(&As[0][0][0]);
    uint32_t sB = (uint32_t)__cvta_generic_to_shared(&Bs[0][0][0]);

#define COPY_STAGE(s, kh)                                                     \
    do {                                                                      \
        uint32_t o1 = (s) * 8192 + (cr * 16) * 4;                             \
        uint32_t o2 = (s) * 8192 + ((cr + 64) * 16) * 4;                      \
        asm volatile("cp.async.cg.shared.global [%0], [%1], 16;"              \
                     :: "r"(sA + o1 + cw * 4), "l"(Asrc0 + (kh)) : "memory"); \
        asm volatile("cp.async.cg.shared.global [%0], [%1], 16;"              \
                     :: "r"(sA + o2 + cw2 * 4), "l"(Asrc1 + (kh)) : "memory");\
        asm volatile("cp.async.cg.shared.global [%0], [%1], 16;"              \
                     :: "r"(sB + o1 + cw * 4), "l"(Bsrc0 + (kh)) : "memory"); \
        asm volatile("cp.async.cg.shared.global [%0], [%1], 16;"              \
                     :: "r"(sB + o2 + cw2 * 4), "l"(Bsrc1 + (kh)) : "memory");\
    } while (0)
#define CP_COMMIT() asm volatile("cp.async.commit_group;" ::: "memory")

    COPY_STAGE(0, 0);  CP_COMMIT();
    COPY_STAGE(1, 32); CP_COMMIT();

    int arow = wm + i8 + (g & 1) * 8;
    int acg  = g >> 1;
    int brow = wn + i8 + (g >> 1) * 8;
    int bcg  = g & 1;

    float acc[4][4][4] = {};
    int NT = K >> 5;
    for (int kt = 0; kt < NT; kt++) {
        int s = kt % 3;
        asm volatile("cp.async.wait_group 1;" ::: "memory");
        __syncthreads();
        int kp = kt + 2;
        if (kp < NT) COPY_STAGE(kp % 3, kp * 32);
        CP_COMMIT();

        uint32_t stoff = s * 8192;
#pragma unroll
        for (int kc = 0; kc < 2; kc++) {
            uint32_t af[4][4], bf[4][2];
#pragma unroll
            for (int mt = 0; mt < 4; mt++) {
                int r = arow + mt * 16;
                int w = r * 16 + 4 * ((2 * kc + acg) ^ ((r >> 1) & 3));
                LDSM_X4(af[mt][0], af[mt][1], af[mt][2], af[mt][3],
                        sA + stoff + w * 4);
            }
#pragma unroll
            for (int nt2 = 0; nt2 < 2; nt2++) {
                int r = brow + nt2 * 16;
                int w = r * 16 + 4 * ((2 * kc + bcg) ^ ((r >> 1) & 3));
                LDSM_X4(bf[nt2 * 2][0], bf[nt2 * 2][1],
                        bf[nt2 * 2 + 1][0], bf[nt2 * 2 + 1][1],
                        sB + stoff + w * 4);
            }
#pragma unroll
            for (int mt = 0; mt < 4; mt++)
#pragma unroll
                for (int nt = 0; nt < 4; nt++)
                    mma_f16(acc[mt][nt], af[mt], bf[nt]);
        }
    }

#pragma unroll
    for (int mt = 0; mt < 4; mt++) {
        int row = m0 + wm + mt * 16 + qr;
#pragma unroll
        for (int nt = 0; nt < 4; nt++) {
            int col = n0 + wn + nt * 8 + qc * 2;
            *reinterpret_cast<float2*>(C + (size_t)row * N + col) =
                make_float2(acc[mt][nt][0], acc[mt][nt][1]);
            *reinterpret_cast<float2*>(C + (size_t)(row + 8) * N + col) =
                make_float2(acc[mt][nt][2], acc[mt][nt][3]);
        }
    }
#undef COPY_STAGE
#undef CP_COMMIT
}

// ---------------- 1) ss = condition @ w_ada^T  (warp per output) ---------
__global__ void ada_kernel(const float* __restrict__ cond,
                           const float* __restrict__ w_ada) {
    int w    = (blockIdx.x * blockDim.x + threadIdx.x) >> 5;
    int lane = threadIdx.x & 31;
    int b = w >> 12;
    int j = w & 4095;
    const float4* c4 = reinterpret_cast<const float4*>(cond + (size_t)b * DC_);
    const float4* w4 = reinterpret_cast<const float4*>(w_ada + (size_t)j * DC_);
    float s = 0.f;
#pragma unroll
    for (int q = 0; q < 16; q++) {
        float4 a  = c4[lane + q * 32];
        float4 bb = w4[lane + q * 32];
        s += a.x * bb.x + a.y * bb.y + a.z * bb.z + a.w * bb.w;
    }
#pragma unroll
    for (int o = 16; o; o >>= 1) s += __shfl_xor_sync(0xffffffffu, s, o);
    if (lane == 0) g_ss[b * 4096 + j] = s;
}

// ------- 2) h = fp16(rmsnorm(x)*(1+scale)+shift) -------------------------
__global__ void rmsada_kernel(const float* __restrict__ x) {
    int row = blockIdx.x;
    int b   = row >> 11;
    int t   = threadIdx.x;
    const float4* xr = reinterpret_cast<const float4*>(x + (size_t)row * D_);
    float4 v0 = xr[t], v1 = xr[t + 256];
    float s = v0.x*v0.x + v0.y*v0.y + v0.z*v0.z + v0.w*v0.w
            + v1.x*v1.x + v1.y*v1.y + v1.z*v1.z + v1.w*v1.w;
    __shared__ float red[256];
    red[t] = s; __syncthreads();
    for (int o = 128; o; o >>= 1) { if (t < o) red[t] += red[t + o]; __syncthreads(); }
    float inv = rsqrtf(red[0] * (1.0f / D_) + EPS);
    const float* shift = g_ss + b * 4096;
    const float* scale = shift + D_;
    uint2* hr = reinterpret_cast<uint2*>(g_hh + (size_t)row * D_);
    {
        int d = t * 4;
        float4 sc = *reinterpret_cast<const float4*>(scale + d);
        float4 sh = *reinterpret_cast<const float4*>(shift + d);
        hr[t] = make_uint2(
            pack_h2(v0.x * inv * (1.f + sc.x) + sh.x,
                    v0.y * inv * (1.f + sc.y) + sh.y),
            pack_h2(v0.z * inv * (1.f + sc.z) + sh.z,
                    v0.w * inv * (1.f + sc.w) + sh.w));
    }
    {
        int d = (t + 256) * 4;
        float4 sc = *reinterpret_cast<const float4*>(scale + d);
        float4 sh = *reinterpret_cast<const float4*>(shift + d);
        hr[t + 256] = make_uint2(
            pack_h2(v1.x * inv * (1.f + sc.x) + sh.x,
                    v1.y * inv * (1.f + sc.y) + sh.y),
            pack_h2(v1.z * inv * (1.f + sc.z) + sh.z,
                    v1.w * inv * (1.f + sc.w) + sh.w));
    }
}

// ------- 4) per-head rmsnorm + qk_w + RoPE -> fp16 q/k/v -----------------
__global__ void qkrope_kernel(const float* __restrict__ rope,
                              const float* __restrict__ qkw) {
    int wid  = (blockIdx.x * blockDim.x + threadIdx.x) >> 5;  // (b*32+h)*2048+l
    int lane = threadIdx.x & 31;
    int b   = wid >> 16;
    int rem = wid & 65535;
    int h   = rem >> 11;
    int l   = rem & 2047;
    size_t rowoff = (size_t)(b * L_ + l) * (3 * D_);
    int col = h * HD_ + lane * 2;
    float2 q = *reinterpret_cast<const float2*>(g_qkv + rowoff + col);
    float2 k = *reinterpret_cast<const float2*>(g_qkv + rowoff + D_ + col);
    float2 v = *reinterpret_cast<const float2*>(g_qkv + rowoff + 2 * D_ + col);
    float sq = q.x * q.x + q.y * q.y;
    float sk = k.x * k.x + k.y * k.y;
#pragma unroll
    for (int o = 16; o; o >>= 1) {
        sq += __shfl_xor_sync(0xffffffffu, sq, o);
        sk += __shfl_xor_sync(0xffffffffu, sk, o);
    }
    float qi = rsqrtf(sq * (1.0f / HD_) + EPS);
    float ki = rsqrtf(sk * (1.0f / HD_) + EPS);
    float2 w2 = *reinterpret_cast<const float2*>(qkw + lane * 2);
    float q0 = q.x * qi * w2.x, q1 = q.y * qi * w2.y;
    float k0 = k.x * ki * w2.x, k1 = k.y * ki * w2.y;
    float2 r0 = *reinterpret_cast<const float2*>(rope + (size_t)l * HD_ + lane * 2);
    float2 r1 = *reinterpret_cast<const float2*>(rope + (size_t)(L_ + l) * HD_ + lane * 2);
    float2 qo, ko;
    qo.x = q0 * r0.x - q1 * r1.x;
    qo.y = q1 * r0.y + q0 * r1.y;
    ko.x = k0 * r0.x - k1 * r1.x;
    ko.y = k1 * r0.y + k0 * r1.y;
    size_t orow = (size_t)wid * HD_ + lane * 2;
    *reinterpret_cast<uint32_t*>(g_qh + orow) = pack_h2(qo.x * 0.125f, qo.y * 0.125f);
    *reinterpret_cast<uint32_t*>(g_kh + orow) = pack_h2(ko.x, ko.y);
    *reinterpret_cast<uint32_t*>(g_vh + orow) = pack_h2(v.x, v.y);
}

// ============ 5) fp16 flash attention: BQ=128, register P ================
// 256 threads (8 warps x 16 q-rows), BC=32, double-buffered K/V, 1 sync/chunk.
__global__ void __launch_bounds__(256, 2) attn_h() {
    __shared__ uint32_t Qs[128][32];     // Q swizzled (rows: 64 halves)
    __shared__ uint32_t Ks[2][32][32];   // K chunk, swizzled
    __shared__ __half   Vt[2][64][34];   // V transposed [d][key]

    int tid  = threadIdx.x;
    int wid  = tid >> 5, lane = tid & 31;
    int qr   = lane >> 2, qc = lane & 3;
    int i8   = lane & 7, g = lane >> 3;
    int bh   = blockIdx.y;
    int bq0  = blockIdx.x * 128;
    int qrow = wid * 16;                 // warp's rows qrow..qrow+15

    const __half* Qg = g_qh + (size_t)bh * L_ * HD_;
    const __half* Kg = g_kh + (size_t)bh * L_ * HD_;
    const __half* Vg = g_vh + (size_t)bh * L_ * HD_;

    // prefetch chunk 0 (32 keys x 64 halves; thread -> row=tid>>3, chunk=tid&7)
    int pr = tid >> 3, pch = tid & 7;
    uint4 kp = *reinterpret_cast<const uint4*>(Kg + (size_t)pr * HD_ + pch * 8);
    uint4 vp = *reinterpret_cast<const uint4*>(Vg + (size_t)pr * HD_ + pch * 8);

    // stage Q: 128 rows x 8 chunks
#pragma unroll
    for (int t = 0; t < 4; t++) {
        int idx = tid + t * 256;
        int r = idx >> 3, ch = idx & 7;
        uint4 u = *reinterpret_cast<const uint4*>(Qg + (size_t)(bq0 + r) * HD_ + ch * 8);
        *reinterpret_cast<uint4*>(&Qs[r][(ch * 4) ^ ((r & 7) << 2)]) = u;
    }
    __syncthreads();

    // Q fragments via ldmatrix (held all kernel)
    uint32_t aq[4][4];
    uint32_t qbase = (uint32_t)__cvta_generic_to_shared(&Qs[0][0]);
    {
        int r = qrow + i8 + (g & 1) * 8;
#pragma unroll
        for (int kk = 0; kk < 4; kk++) {
            int ch = 2 * kk + (g >> 1);
            int w = r * 32 + ((ch * 4) ^ ((r & 7) << 2));
            LDSM_X4(aq[kk][0], aq[kk][1], aq[kk][2], aq[kk][3], qbase + w * 4);
        }
    }

    // store chunk 0 into buffer 0
    {
        *reinterpret_cast<uint4*>(&Ks[0][pr][(pch * 4) ^ ((pr & 7) << 2)]) = kp;
        __half vh[8];
        *reinterpret_cast<uint4*>(vh) = vp;
#pragma unroll
        for (int i = 0; i < 8; i++) Vt[0][pch * 8 + i][pr] = vh[i];
    }
    __syncthreads();

    uint32_t kbase = (uint32_t)__cvta_generic_to_shared(&Ks[0][0][0]);
    int krow = i8 + (g >> 1) * 8;        // + j2*16

    float o[8][4] = {};
    float m_lo = -INFINITY, m_hi = -INFINITY, l_lo = 0.f, l_hi = 0.f;
    int p = 0;

    for (int c = 0; c < 64; c++) {
        // issue prefetch for next chunk
        if (c < 63) {
            size_t koff = (size_t)(c + 1) * 32;
            kp = *reinterpret_cast<const uint4*>(Kg + (koff + pr) * HD_ + pch * 8);
            vp = *reinterpret_cast<const uint4*>(Vg + (koff + pr) * HD_ + pch * 8);
        }

        // ---- S = Q K^T : per warp m16 x n32, K frags via ldmatrix ----
        float s[4][4] = {};
        uint32_t pbase = kbase + p * 4096;
#pragma unroll
        for (int kk = 0; kk < 4; kk++) {
            uint32_t b0[4], b1[4];
            {
                int r = krow;
                int ch = 2 * kk + (g & 1);
                int w = r * 32 + ((ch * 4) ^ ((r & 7) << 2));
                LDSM_X4(b0[0], b0[1], b0[2], b0[3], pbase + w * 4);
            }
            {
                int r = krow + 16;
                int ch = 2 * kk + (g & 1);
                int w = r * 32 + ((ch * 4) ^ ((r & 7) << 2));
                LDSM_X4(b1[0], b1[1], b1[2], b1[3], pbase + w * 4);
            }
            mma_f16(s[0], aq[kk], b0);
            mma_f16(s[1], aq[kk], b0 + 2);
            mma_f16(s[2], aq[kk], b1);
            mma_f16(s[3], aq[kk], b1 + 2);
        }

        // ---- online softmax (fragment layout) ----
        float mx_lo = -INFINITY, mx_hi = -INFINITY;
#pragma unroll
        for (int j = 0; j < 4; j++) {
            mx_lo = fmaxf(mx_lo, fmaxf(s[j][0], s[j][1]));
            mx_hi = fmaxf(mx_hi, fmaxf(s[j][2], s[j][3]));
        }
        mx_lo = fmaxf(mx_lo, __shfl_xor_sync(0xffffffffu, mx_lo, 1));
        mx_lo = fmaxf(mx_lo, __shfl_xor_sync(0xffffffffu, mx_lo, 2));
        mx_hi = fmaxf(mx_hi, __shfl_xor_sync(0xffffffffu, mx_hi, 1));
        mx_hi = fmaxf(mx_hi, __shfl_xor_sync(0xffffffffu, mx_hi, 2));

        float mn_lo = fmaxf(m_lo, mx_lo);
        float mn_hi = fmaxf(m_hi, mx_hi);
        float cf_lo = __expf(m_lo - mn_lo);
        float cf_hi = __expf(m_hi - mn_hi);
        m_lo = mn_lo; m_hi = mn_hi;

        // P in registers: C-frag of S -> A-frag of PV (pack_h2 rounds to fp16)
        uint32_t ap[2][4];
        float ls_lo = 0.f, ls_hi = 0.f;
#pragma unroll
        for (int kk2 = 0; kk2 < 2; kk2++) {
#pragma unroll
            for (int jj = 0; jj < 2; jj++) {
                int j = 2 * kk2 + jj;
                uint32_t plo = pack_h2(__expf(s[j][0] - mn_lo),
                                       __expf(s[j][1] - mn_lo));
                uint32_t phi = pack_h2(__expf(s[j][2] - mn_hi),
                                       __expf(s[j][3] - mn_hi));
                ap[kk2][2 * jj]     = plo;
                ap[kk2][2 * jj + 1] = phi;
                float2 flo = unpack_h2(plo), fhi = unpack_h2(phi);
                ls_lo += flo.x + flo.y;   // l from rounded P
                ls_hi += fhi.x + fhi.y;
            }
        }
        ls_lo += __shfl_xor_sync(0xffffffffu, ls_lo, 1);
        ls_lo += __shfl_xor_sync(0xffffffffu, ls_lo, 2);
        ls_hi += __shfl_xor_sync(0xffffffffu, ls_hi, 1);
        ls_hi += __shfl_xor_sync(0xffffffffu, ls_hi, 2);
        l_lo = l_lo * cf_lo + ls_lo;
        l_hi = l_hi * cf_hi + ls_hi;

#pragma unroll
        for (int n = 0; n < 8; n++) {
            o[n][0] *= cf_lo; o[n][1] *= cf_lo;
            o[n][2] *= cf_hi; o[n][3] *= cf_hi;
        }

        // ---- O += P V (V from transposed smem) ----
#pragma unroll
        for (int kk2 = 0; kk2 < 2; kk2++) {
#pragma unroll
            for (int n = 0; n < 8; n++) {
                int vr = 8 * n + qr;
                uint32_t bv[2];
                bv[0] = *reinterpret_cast<const uint32_t*>(
                            &Vt[p][vr][2 * (8 * kk2 + qc)]);
                bv[1] = *reinterpret_cast<const uint32_t*>(
                            &Vt[p][vr][2 * (8 * kk2 + qc + 4)]);
                mma_f16(o[n], ap[kk2], bv);
            }
        }

        // store prefetched chunk into other buffer, single sync
        if (c < 63) {
            int np = p ^ 1;
            *reinterpret_cast<uint4*>(&Ks[np][pr][(pch * 4) ^ ((pr & 7) << 2)]) = kp;
            __half vh[8];
            *reinterpret_cast<uint4*>(vh) = vp;
#pragma unroll
            for (int i = 0; i < 8; i++) Vt[np][pch * 8 + i][pr] = vh[i];
            __syncthreads();
            p = np;
        }
    }

    // epilogue: normalize, fp16, store rows=(b,l), cols=(h,d)
    int b = bh >> 5, h = bh & 31;
    float inv_lo = 1.f / l_lo, inv_hi = 1.f / l_hi;
    __half* base_lo = g_oh + (size_t)(b * L_ + bq0 + qrow + qr) * D_ + h * HD_;
    __half* base_hi = g_oh + (size_t)(b * L_ + bq0 + qrow + qr + 8) * D_ + h * HD_;
#pragma unroll
    for (int n = 0; n < 8; n++) {
        *reinterpret_cast<uint32_t*>(base_lo + 8 * n + 2 * qc) =
            pack_h2(o[n][0] * inv_lo, o[n][1] * inv_lo);
        *reinterpret_cast<uint32_t*>(base_hi + 8 * n + 2 * qc) =
            pack_h2(o[n][2] * inv_hi, o[n][3] * inv_hi);
    }
}

// -------------------------------------------------------------------------
extern "C" void kernel_launch(void* const* d_in, const int* in_sizes, int n_in,
                              void* d_out, int out_size) {
    const float* x     = (const float*)d_in[0];
    const float* cond  = (const float*)d_in[1];
    const float* rope  = (const float*)d_in[2];
    const float* w_ada = (const float*)d_in[3];
    const float* w_qkv = (const float*)d_in[4];
    const float* w_out = (const float*)d_in[5];
    const float* qk_w  = (const float*)d_in[6];
    float* out = (float*)d_out;

    void* p;
    cudaGetSymbolAddress(&p, g_qkv); float*  pqkv = (float*)p;
    cudaGetSymbolAddress(&p, g_hh);  __half* phh  = (__half*)p;
    cudaGetSymbolAddress(&p, g_wqh); __half* pwq  = (__half*)p;
    cudaGetSymbolAddress(&p, g_woh); __half* pwo  = (__half*)p;
    cudaGetSymbolAddress(&p, g_oh);  __half* poh  = (__half*)p;

    cvtw_h<<<3 * D_ * D_ / 1024, 256>>>(pwq, w_qkv);
    cvtw_h<<<D_ * D_ / 1024, 256>>>(pwo, w_out);
    ada_kernel<<<1024, 256>>>(cond, w_ada);
    rmsada_kernel<<<B_ * L_, 256>>>(x);
    gemm_h<<<dim3(3 * D_ / 128, B_ * L_ / 128), 256>>>(pqkv, phh, pwq,
                                                       B_ * L_, 3 * D_, D_);
    qkrope_kernel<<<(B_ * NH_ * L_) / 8, 256>>>(rope, qk_w);
    attn_h<<<dim3(L_ / 128, B_ * NH_), 256>>>();
    gemm_h<<<dim3(D_ / 128, B_ * L_ / 128), 256>>>(out, poh, pwo,
                                                   B_ * L_, D_, D_);
}